// round 8
// baseline (speedup 1.0000x reference)
#include <cuda_runtime.h>
#include <math.h>

// Row-normalize: out[r, c] = in[r, c] / sum_c in[r, c]
// 65536 rows of 1024 floats.
// Persistent software-pipelined kernel: one warp handles many rows.
// While reducing/storing row i, the 8 LDG.128s of row i+1 are already
// in flight -> read stream never drains during the write burst.

static constexpr int ROW_LEN     = 1024;
static constexpr int V4_PER_ROW  = ROW_LEN / 4;     // 256 float4 per row
static constexpr int V4_PER_LANE = V4_PER_ROW / 32; // 8 float4 per lane
static constexpr int THREADS     = 256;             // 8 warps per CTA
static constexpr int WARPS       = THREADS / 32;
static constexpr int NUM_SMS     = 148;             // GB300 has 152; 148 safe
static constexpr int CTAS_PER_SM = 3;               // ~85 regs -> 3 CTAs resident

__global__ __launch_bounds__(THREADS)
void normalizer_kernel(const float* __restrict__ in, float* __restrict__ out,
                       int n_rows) {
    const int lane  = threadIdx.x & 31;
    const int wid   = threadIdx.x >> 5;
    const int gwarp = blockIdx.x * WARPS + wid;
    const int W     = gridDim.x * WARPS;            // total warps

    const float4* in4  = reinterpret_cast<const float4*>(in);
    float4*       out4 = reinterpret_cast<float4*>(out);

    float4 cur[V4_PER_LANE], nxt[V4_PER_LANE];

    long long r = gwarp;
    if (r < n_rows) {
        const float4* p = in4 + r * V4_PER_ROW + lane;
        #pragma unroll
        for (int i = 0; i < V4_PER_LANE; i++)
            cur[i] = __ldcs(p + i * 32);
    }

    for (; r < n_rows; r += W) {
        // Prefetch next row BEFORE consuming current one: these 8 LDGs stay
        // outstanding across the reduce + store of the current row.
        const long long rn = r + W;
        if (rn < n_rows) {
            const float4* p = in4 + rn * V4_PER_ROW + lane;
            #pragma unroll
            for (int i = 0; i < V4_PER_LANE; i++)
                nxt[i] = __ldcs(p + i * 32);
        }

        // Reduce current row
        float s = 0.0f;
        #pragma unroll
        for (int i = 0; i < V4_PER_LANE; i++)
            s += (cur[i].x + cur[i].y) + (cur[i].z + cur[i].w);

        #pragma unroll
        for (int off = 16; off > 0; off >>= 1)
            s += __shfl_xor_sync(0xFFFFFFFFu, s, off);

        float inv = 1.0f / s;
        inv = isfinite(inv) ? inv : 0.0f;

        // Scale + streaming store
        float4* q = out4 + r * V4_PER_ROW + lane;
        #pragma unroll
        for (int i = 0; i < V4_PER_LANE; i++) {
            float4 o;
            o.x = cur[i].x * inv;
            o.y = cur[i].y * inv;
            o.z = cur[i].z * inv;
            o.w = cur[i].w * inv;
            __stcs(q + i * 32, o);
        }

        // Rotate buffers (register moves; cheap vs 4 KB of traffic per row)
        #pragma unroll
        for (int i = 0; i < V4_PER_LANE; i++)
            cur[i] = nxt[i];
    }
}

extern "C" void kernel_launch(void* const* d_in, const int* in_sizes, int n_in,
                              void* d_out, int out_size) {
    const float* adj = (const float*)d_in[0];
    float* out = (float*)d_out;
    const long long total = (long long)in_sizes[0];      // 2*32*1024*1024
    const int n_rows = (int)(total / ROW_LEN);            // 65536
    const int n_blocks = NUM_SMS * CTAS_PER_SM;           // persistent grid
    normalizer_kernel<<<n_blocks, THREADS>>>(adj, out, n_rows);
}

// round 9
// speedup vs baseline: 1.1054x; 1.1054x over previous
#include <cuda_runtime.h>
#include <math.h>

// Row-normalize: out[r, c] = in[r, c] / sum_c in[r, c]
// 65536 rows of 1024 floats. One WARP per row.
// sm_103a 256-bit vector accesses: each lane does 4x ld.global.cs.v8.f32
// (32 B per lane per instr -> 1024 B per warp-instr), warp-shuffle reduce,
// scale, 4x st.global.cs.v8.f32. Fewer, wider memory transactions.

static constexpr int ROW_LEN = 1024;
static constexpr int CHUNKS  = 4;            // 4 x 256 floats per row
static constexpr int THREADS = 256;          // 8 warps per CTA
static constexpr int WARPS   = THREADS / 32;

__global__ __launch_bounds__(THREADS)
void normalizer_kernel(const float* __restrict__ in, float* __restrict__ out) {
    const int lane = threadIdx.x & 31;
    const int wid  = threadIdx.x >> 5;
    const long long row = (long long)blockIdx.x * WARPS + wid;   // 0 .. 65535

    const float* ip = in  + row * ROW_LEN + lane * 8;
    float*       op = out + row * ROW_LEN + lane * 8;

    // 4 x 256-bit streaming loads per lane (front-batched).
    float v[CHUNKS][8];
    #pragma unroll
    for (int c = 0; c < CHUNKS; c++) {
        asm volatile(
            "ld.global.cs.v8.f32 {%0,%1,%2,%3,%4,%5,%6,%7}, [%8];"
            : "=f"(v[c][0]), "=f"(v[c][1]), "=f"(v[c][2]), "=f"(v[c][3]),
              "=f"(v[c][4]), "=f"(v[c][5]), "=f"(v[c][6]), "=f"(v[c][7])
            : "l"(ip + c * 256));
    }

    // Per-lane partial sum (tree-ish to shorten dep chain)
    float s = 0.0f;
    #pragma unroll
    for (int c = 0; c < CHUNKS; c++) {
        float a = (v[c][0] + v[c][1]) + (v[c][2] + v[c][3]);
        float b = (v[c][4] + v[c][5]) + (v[c][6] + v[c][7]);
        s += a + b;
    }

    // Warp reduce
    #pragma unroll
    for (int off = 16; off > 0; off >>= 1)
        s += __shfl_xor_sync(0xFFFFFFFFu, s, off);

    float inv = 1.0f / s;
    inv = isfinite(inv) ? inv : 0.0f;

    // Scale + 4 x 256-bit streaming stores per lane.
    #pragma unroll
    for (int c = 0; c < CHUNKS; c++) {
        float o0 = v[c][0] * inv, o1 = v[c][1] * inv;
        float o2 = v[c][2] * inv, o3 = v[c][3] * inv;
        float o4 = v[c][4] * inv, o5 = v[c][5] * inv;
        float o6 = v[c][6] * inv, o7 = v[c][7] * inv;
        asm volatile(
            "st.global.cs.v8.f32 [%8], {%0,%1,%2,%3,%4,%5,%6,%7};"
            :: "f"(o0), "f"(o1), "f"(o2), "f"(o3),
               "f"(o4), "f"(o5), "f"(o6), "f"(o7),
               "l"(op + c * 256)
            : "memory");
    }
}

extern "C" void kernel_launch(void* const* d_in, const int* in_sizes, int n_in,
                              void* d_out, int out_size) {
    const float* adj = (const float*)d_in[0];
    float* out = (float*)d_out;
    const long long total = (long long)in_sizes[0];      // 2*32*1024*1024
    const int n_rows = (int)(total / ROW_LEN);            // 65536
    const int n_blocks = n_rows / WARPS;                  // 8192
    normalizer_kernel<<<n_blocks, THREADS>>>(adj, out);
}